// round 14
// baseline (speedup 1.0000x reference)
#include <cuda_runtime.h>
#include <math.h>
#include <stdint.h>

#define DIMN   1024
#define S_LEN  2048
#define BATCH  2
#define NHEAD  16     // 2H attention heads (q/k), dim 64
#define HD     64
#define VD     128    // v head dim (2*hd)
#define M_TOT  (BATCH*S_LEN)   // 4096

#define LAMBDA_INIT 0.70082066706704805f

// ---------------- scratch (static device memory; no runtime allocs) ----------
__device__ float g_q[(size_t)BATCH*S_LEN*DIMN];
__device__ float g_k[(size_t)BATCH*S_LEN*DIMN];
__device__ float g_v[(size_t)BATCH*S_LEN*DIMN];
__device__ float g_oj[(size_t)BATCH*NHEAD*S_LEN*VD];   // per-attn-head O
__device__ float g_att[(size_t)BATCH*S_LEN*DIMN];      // combined, pre-Wo
__device__ float g_lambda;

// ---------------- lambda ------------------------------------------------------
__global__ void lambda_kernel(const float* __restrict__ lq1, const float* __restrict__ lk1,
                              const float* __restrict__ lq2, const float* __restrict__ lk2) {
    if (threadIdx.x == 0) {
        float s1 = 0.f, s2 = 0.f;
        for (int i = 0; i < HD; i++) { s1 += lq1[i]*lk1[i]; s2 += lq2[i]*lk2[i]; }
        g_lambda = expf(s1) - expf(s2) + LAMBDA_INIT;
    }
}

// ---------------- tf32 mma helpers -------------------------------------------
__device__ __forceinline__ uint32_t f2tf32(float x) {
    uint32_t r;
    asm("cvt.rna.tf32.f32 %0, %1;" : "=r"(r) : "f"(x));
    return r;
}
__device__ __forceinline__ float tf32hi(float x) {
    return __uint_as_float(f2tf32(x));
}

__device__ __forceinline__ void mma_tf32(float* c,
                                         uint32_t a0, uint32_t a1, uint32_t a2, uint32_t a3,
                                         uint32_t b0, uint32_t b1) {
    asm volatile("mma.sync.aligned.m16n8k8.row.col.f32.tf32.tf32.f32 "
                 "{%0,%1,%2,%3}, {%4,%5,%6,%7}, {%8,%9}, {%0,%1,%2,%3};\n"
                 : "+f"(c[0]), "+f"(c[1]), "+f"(c[2]), "+f"(c[3])
                 : "r"(a0), "r"(a1), "r"(a2), "r"(a3), "r"(b0), "r"(b1));
}

__device__ __forceinline__ void cp_async16(uint32_t smem_addr, const void* gptr) {
    asm volatile("cp.async.cg.shared.global [%0], [%1], 16;\n"
                 :: "r"(smem_addr), "l"(gptr));
}

// ---------------- NT GEMM via tensor cores (3xTF32, cp.async 2-stage) ---------
// C[m,n] = alpha * sum_k A[m,k]*B[n,k].  BM=BN=128, BK=16, 256 threads (8 warps
// in 2(M)x4(N)); each warp owns a 64x32 tile = 4x4 grid of m16n8k8 mmas.
// Runtime hi/lo split (keeps smem at 40KB, regs <=128 -> 2 CTAs/SM).
__global__ __launch_bounds__(256, 2) void gemm_tf32(const float* __restrict__ A,
                                                    const float* __restrict__ B,
                                                    float* __restrict__ C,
                                                    int M, int N, int K, float alpha) {
    __shared__ float As[2][128][20];
    __shared__ float Bs[2][128][20];
    const int tid  = threadIdx.x;
    const int lane = tid & 31;
    const int w    = tid >> 5;
    const int warp_m = (w & 1) * 64;       // 0 or 64
    const int warp_n = (w >> 1) * 32;      // 0,32,64,96
    const int lr = lane >> 2;              // 0..7
    const int lc = lane & 3;               // 0..3
    const int bm0 = blockIdx.y * 128, bn0 = blockIdx.x * 128;

    const int ldr  = tid >> 2;             // 0..63
    const int ldr2 = ldr + 64;
    const int ldc  = (tid & 3) << 2;

    const uint32_t sA0  = (uint32_t)__cvta_generic_to_shared(&As[0][ldr ][ldc]);
    const uint32_t sA1  = (uint32_t)__cvta_generic_to_shared(&As[0][ldr2][ldc]);
    const uint32_t sB0  = (uint32_t)__cvta_generic_to_shared(&Bs[0][ldr ][ldc]);
    const uint32_t sB1  = (uint32_t)__cvta_generic_to_shared(&Bs[0][ldr2][ldc]);
    const uint32_t bufstride = 128 * 20 * 4;

    const float* gA0 = &A[(size_t)(bm0 + ldr ) * K + ldc];
    const float* gA1 = &A[(size_t)(bm0 + ldr2) * K + ldc];
    const float* gB0 = &B[(size_t)(bn0 + ldr ) * K + ldc];
    const float* gB1 = &B[(size_t)(bn0 + ldr2) * K + ldc];

    float acc[4][4][4];
#pragma unroll
    for (int i = 0; i < 4; i++)
#pragma unroll
        for (int j = 0; j < 4; j++)
#pragma unroll
            for (int r = 0; r < 4; r++) acc[i][j][r] = 0.f;

    // prologue: stage 0 -> buffer 0
    cp_async16(sA0, gA0); cp_async16(sA1, gA1);
    cp_async16(sB0, gB0); cp_async16(sB1, gB1);
    asm volatile("cp.async.commit_group;\n");

    const int NIT = K >> 4;
    int buf = 0;
    for (int it = 0; it < NIT; it++) {
        if (it + 1 < NIT) {
            int kn = (it + 1) << 4;
            uint32_t off = (uint32_t)(buf ^ 1) * bufstride;
            cp_async16(sA0 + off, gA0 + kn); cp_async16(sA1 + off, gA1 + kn);
            cp_async16(sB0 + off, gB0 + kn); cp_async16(sB1 + off, gB1 + kn);
            asm volatile("cp.async.commit_group;\n");
            asm volatile("cp.async.wait_group 1;\n");
        } else {
            asm volatile("cp.async.wait_group 0;\n");
        }
        __syncthreads();

#pragma unroll
        for (int ks = 0; ks < 16; ks += 8) {
            uint32_t bh[4][2], bl[4][2];
#pragma unroll
            for (int nt = 0; nt < 4; nt++) {
                int rn = warp_n + nt * 8 + lr;
                float b0 = Bs[buf][rn][ks + lc];
                float b1 = Bs[buf][rn][ks + lc + 4];
                bh[nt][0] = f2tf32(b0); bl[nt][0] = __float_as_uint(b0 - __uint_as_float(bh[nt][0]));
                bh[nt][1] = f2tf32(b1); bl[nt][1] = __float_as_uint(b1 - __uint_as_float(bh[nt][1]));
            }
#pragma unroll
            for (int mt = 0; mt < 4; mt++) {
                int r0 = warp_m + mt * 16 + lr;
                float a0 = As[buf][r0    ][ks + lc];
                float a1 = As[buf][r0 + 8][ks + lc];
                float a2 = As[buf][r0    ][ks + lc + 4];
                float a3 = As[buf][r0 + 8][ks + lc + 4];
                uint32_t ah0 = f2tf32(a0), ah1 = f2tf32(a1), ah2 = f2tf32(a2), ah3 = f2tf32(a3);
                uint32_t al0 = __float_as_uint(a0 - __uint_as_float(ah0));
                uint32_t al1 = __float_as_uint(a1 - __uint_as_float(ah1));
                uint32_t al2 = __float_as_uint(a2 - __uint_as_float(ah2));
                uint32_t al3 = __float_as_uint(a3 - __uint_as_float(ah3));
#pragma unroll
                for (int nt = 0; nt < 4; nt++) {
                    mma_tf32(acc[mt][nt], ah0, ah1, ah2, ah3, bh[nt][0], bh[nt][1]);
                    mma_tf32(acc[mt][nt], ah0, ah1, ah2, ah3, bl[nt][0], bl[nt][1]);
                    mma_tf32(acc[mt][nt], al0, al1, al2, al3, bh[nt][0], bh[nt][1]);
                }
            }
        }
        __syncthreads();
        buf ^= 1;
    }

#pragma unroll
    for (int mt = 0; mt < 4; mt++) {
#pragma unroll
        for (int nt = 0; nt < 4; nt++) {
            int row = bm0 + warp_m + mt * 16 + lr;
            int col = bn0 + warp_n + nt * 8 + lc * 2;
            float2 lo = make_float2(alpha * acc[mt][nt][0], alpha * acc[mt][nt][1]);
            float2 hi = make_float2(alpha * acc[mt][nt][2], alpha * acc[mt][nt][3]);
            *(float2*)&C[(size_t)row * N + col]       = lo;
            *(float2*)&C[(size_t)(row + 8) * N + col] = hi;
        }
    }
}

// ---------------- flash attention, tensor-core version ------------------------
// BM=128 q rows, BN=64 keys/iter, hd=64, VD=128. 256 threads = 8 warps, each
// warp owns 16 q rows (softmax state warp-local). QK = 3xTF32, PV = 1xTF32.
// smem floats: Qh/Ql 128x68, Kh/Kl 64x68, V 64x136, P 128x68  -> 174080 B
#define FL_QS 68
#define FL_VS 136
#define FLASH_SMEM_FLOATS (2*128*FL_QS + 2*64*FL_QS + 64*FL_VS + 128*FL_QS)
#define FLASH_SMEM_BYTES  (FLASH_SMEM_FLOATS * 4)

__global__ __launch_bounds__(256, 1) void flash_mma_kernel(const float* __restrict__ q,
                                                           const float* __restrict__ k,
                                                           const float* __restrict__ v,
                                                           float* __restrict__ oj) {
    extern __shared__ float sm[];
    float (*Qh)[FL_QS] = (float (*)[FL_QS])sm;
    float (*Ql)[FL_QS] = (float (*)[FL_QS])(sm + 128 * FL_QS);
    float (*Kh)[FL_QS] = (float (*)[FL_QS])(sm + 2 * 128 * FL_QS);
    float (*Kl)[FL_QS] = (float (*)[FL_QS])(sm + 2 * 128 * FL_QS + 64 * FL_QS);
    float (*Vs)[FL_VS] = (float (*)[FL_VS])(sm + 2 * 128 * FL_QS + 2 * 64 * FL_QS);
    float (*Ps)[FL_QS] = (float (*)[FL_QS])(sm + 2 * 128 * FL_QS + 2 * 64 * FL_QS + 64 * FL_VS);

    const int tid  = threadIdx.x;
    const int lane = tid & 31;
    const int w    = tid >> 5;
    const int wm   = w * 16;               // warp's 16 q rows
    const int lr   = lane >> 2;            // 0..7
    const int lc   = lane & 3;             // 0..3
    const int qb   = (gridDim.x - 1) - blockIdx.x;   // big tiles first
    const int h    = blockIdx.y;
    const int b    = blockIdx.z;
    const int hv   = h >> 1;

    const float* qbase = q + ((size_t)(b * S_LEN + qb * 128)) * DIMN + h * HD;
    const float* kbase = k + (size_t)b * S_LEN * DIMN + h * HD;
    const float* vbase = v + (size_t)b * S_LEN * DIMN + hv * VD;

    // load Q tile 128x64, split hi/lo. 2048 float4, 8 per thread.
#pragma unroll
    for (int u = 0; u < 8; u++) {
        int idx = tid + u * 256;
        int row = idx >> 4;
        int c4  = (idx & 15) << 2;
        float4 x = *(const float4*)&qbase[(size_t)row * DIMN + c4];
        float4 hh, ll;
        hh.x=tf32hi(x.x); hh.y=tf32hi(x.y); hh.z=tf32hi(x.z); hh.w=tf32hi(x.w);
        ll.x=x.x-hh.x; ll.y=x.y-hh.y; ll.z=x.z-hh.z; ll.w=x.w-hh.w;
        *(float4*)&Qh[row][c4] = hh;
        *(float4*)&Ql[row][c4] = ll;
    }

    float mrow[2], lrow[2];
    float o[16][4];
    mrow[0] = mrow[1] = -1e30f;
    lrow[0] = lrow[1] = 0.f;
#pragma unroll
    for (int i = 0; i < 16; i++)
#pragma unroll
        for (int r = 0; r < 4; r++) o[i][r] = 0.f;

    const int ktiles = 2 * qb + 2;
    for (int kt = 0; kt < ktiles; kt++) {
        __syncthreads();
        // load K tile 64x64 (split hi/lo): 1024 float4, 4/thread
#pragma unroll
        for (int u = 0; u < 4; u++) {
            int idx = tid + u * 256;
            int row = idx >> 4;
            int c4  = (idx & 15) << 2;
            float4 x = *(const float4*)&kbase[(size_t)(kt * 64 + row) * DIMN + c4];
            float4 hh, ll;
            hh.x=tf32hi(x.x); hh.y=tf32hi(x.y); hh.z=tf32hi(x.z); hh.w=tf32hi(x.w);
            ll.x=x.x-hh.x; ll.y=x.y-hh.y; ll.z=x.z-hh.z; ll.w=x.w-hh.w;
            *(float4*)&Kh[row][c4] = hh;
            *(float4*)&Kl[row][c4] = ll;
        }
        // load V tile 64x128 (tf32-rounded): 2048 float4, 8/thread
#pragma unroll
        for (int u = 0; u < 8; u++) {
            int idx = tid + u * 256;
            int row = idx >> 5;
            int c4  = (idx & 31) << 2;
            float4 x = *(const float4*)&vbase[(size_t)(kt * 64 + row) * DIMN + c4];
            x.x=tf32hi(x.x); x.y=tf32hi(x.y); x.z=tf32hi(x.z); x.w=tf32hi(x.w);
            *(float4*)&Vs[row][c4] = x;
        }
        __syncthreads();

        // ---- S = Q K^T via 3xTF32: 8 n8-tiles x 8 k-steps ----
        float s[8][4];
#pragma unroll
        for (int nt = 0; nt < 8; nt++)
#pragma unroll
            for (int r = 0; r < 4; r++) s[nt][r] = 0.f;

#pragma unroll
        for (int ks = 0; ks < 64; ks += 8) {
            int r0 = wm + lr;
            uint32_t ah0 = __float_as_uint(Qh[r0    ][ks + lc]);
            uint32_t ah1 = __float_as_uint(Qh[r0 + 8][ks + lc]);
            uint32_t ah2 = __float_as_uint(Qh[r0    ][ks + lc + 4]);
            uint32_t ah3 = __float_as_uint(Qh[r0 + 8][ks + lc + 4]);
            uint32_t al0 = __float_as_uint(Ql[r0    ][ks + lc]);
            uint32_t al1 = __float_as_uint(Ql[r0 + 8][ks + lc]);
            uint32_t al2 = __float_as_uint(Ql[r0    ][ks + lc + 4]);
            uint32_t al3 = __float_as_uint(Ql[r0 + 8][ks + lc + 4]);
#pragma unroll
            for (int nt = 0; nt < 8; nt++) {
                int rn = nt * 8 + lr;
                uint32_t bh0 = __float_as_uint(Kh[rn][ks + lc]);
                uint32_t bh1 = __float_as_uint(Kh[rn][ks + lc + 4]);
                uint32_t bl0 = __float_as_uint(Kl[rn][ks + lc]);
                uint32_t bl1 = __float_as_uint(Kl[rn][ks + lc + 4]);
                mma_tf32(s[nt], ah0, ah1, ah2, ah3, bh0, bh1);
                mma_tf32(s[nt], ah0, ah1, ah2, ah3, bl0, bl1);
                mma_tf32(s[nt], al0, al1, al2, al3, bh0, bh1);
            }
        }

        // ---- causal mask on diagonal tiles ----
        if (kt >= 2 * qb) {
            int koff = kt * 64 - qb * 128;   // 0 or 64
            int r0 = wm + lr, r1 = wm + lr + 8;
#pragma unroll
            for (int nt = 0; nt < 8; nt++) {
                int c0 = koff + nt * 8 + lc * 2;
                int c1 = c0 + 1;
                if (c0 > r0) s[nt][0] = -1e30f;
                if (c1 > r0) s[nt][1] = -1e30f;
                if (c0 > r1) s[nt][2] = -1e30f;
                if (c1 > r1) s[nt][3] = -1e30f;
            }
        }

        // ---- online softmax (rows lr and lr+8, quad-wide reductions) ----
#pragma unroll
        for (int half = 0; half < 2; half++) {
            float mt = -1e30f;
#pragma unroll
            for (int nt = 0; nt < 8; nt++)
                mt = fmaxf(mt, fmaxf(s[nt][2*half], s[nt][2*half+1]));
            mt = fmaxf(mt, __shfl_xor_sync(0xffffffffu, mt, 1));
            mt = fmaxf(mt, __shfl_xor_sync(0xffffffffu, mt, 2));
            float mn = fmaxf(mrow[half], mt);
            float sc = __expf(mrow[half] - mn);
            float ps = 0.f;
#pragma unroll
            for (int nt = 0; nt < 8; nt++) {
                float e0 = __expf(s[nt][2*half]   - mn);
                float e1 = __expf(s[nt][2*half+1] - mn);
                ps += e0 + e1;
                s[nt][2*half]   = e0;
                s[nt][2*half+1] = e1;
            }
            ps += __shfl_xor_sync(0xffffffffu, ps, 1);
            ps += __shfl_xor_sync(0xffffffffu, ps, 2);
            lrow[half] = lrow[half] * sc + ps;
            mrow[half] = mn;
#pragma unroll
            for (int nt = 0; nt < 16; nt++) {
                o[nt][2*half]   *= sc;
                o[nt][2*half+1] *= sc;
            }
        }

        // ---- stage P (tf32-rounded) to this warp's smem rows ----
        {
            int r0 = wm + lr, r1 = wm + lr + 8;
#pragma unroll
            for (int nt = 0; nt < 8; nt++) {
                int c = nt * 8 + lc * 2;
                Ps[r0][c]     = tf32hi(s[nt][0]);
                Ps[r0][c + 1] = tf32hi(s[nt][1]);
                Ps[r1][c]     = tf32hi(s[nt][2]);
                Ps[r1][c + 1] = tf32hi(s[nt][3]);
            }
        }
        __syncwarp();

        // ---- O += P @ V : 16 vd n8-tiles x 8 k-steps ----
#pragma unroll
        for (int ks = 0; ks < 64; ks += 8) {
            int r0 = wm + lr;
            uint32_t a0 = __float_as_uint(Ps[r0    ][ks + lc]);
            uint32_t a1 = __float_as_uint(Ps[r0 + 8][ks + lc]);
            uint32_t a2 = __float_as_uint(Ps[r0    ][ks + lc + 4]);
            uint32_t a3 = __float_as_uint(Ps[r0 + 8][ks + lc + 4]);
#pragma unroll
            for (int nt = 0; nt < 16; nt++) {
                uint32_t b0 = __float_as_uint(Vs[ks + lc    ][nt * 8 + lr]);
                uint32_t b1 = __float_as_uint(Vs[ks + lc + 4][nt * 8 + lr]);
                mma_tf32(o[nt], a0, a1, a2, a3, b0, b1);
            }
        }
    }

    // ---- epilogue: O /= l, store ----
    float* obase = oj + (((size_t)(b * NHEAD + h)) * S_LEN + qb * 128) * VD;
    float inv0 = 1.f / lrow[0];
    float inv1 = 1.f / lrow[1];
    int r0 = wm + lr, r1 = wm + lr + 8;
#pragma unroll
    for (int nt = 0; nt < 16; nt++) {
        int c = nt * 8 + lc * 2;
        *(float2*)&obase[(size_t)r0 * VD + c] = make_float2(o[nt][0] * inv0, o[nt][1] * inv0);
        *(float2*)&obase[(size_t)r1 * VD + c] = make_float2(o[nt][2] * inv1, o[nt][3] * inv1);
    }
}

// ---------------- combine pairs + RMSNorm -------------------------------------
__global__ void combine_kernel(const float* __restrict__ oj, float* __restrict__ att) {
    const int bid = blockIdx.x;
    const int hv = bid & 7;
    const int s  = (bid >> 3) & (S_LEN - 1);
    const int b  = bid >> 14;
    const int d  = threadIdx.x;

    const float lam = g_lambda;
    size_t i0 = (((size_t)(b * NHEAD + 2 * hv)) * S_LEN + s) * VD + d;
    size_t i1 = i0 + (size_t)S_LEN * VD;
    float val = oj[i0] - lam * oj[i1];

    float v2 = val * val;
#pragma unroll
    for (int off = 16; off > 0; off >>= 1)
        v2 += __shfl_xor_sync(0xffffffffu, v2, off);
    __shared__ float red[4];
    if ((d & 31) == 0) red[d >> 5] = v2;
    __syncthreads();
    float tot = red[0] + red[1] + red[2] + red[3];
    float rms = rsqrtf(tot * (1.0f / 128.0f) + 1e-5f);
    att[((size_t)(b * S_LEN) + s) * DIMN + hv * VD + d] = val * rms * (1.0f - LAMBDA_INIT);
}

// ---------------- launch ------------------------------------------------------
extern "C" void kernel_launch(void* const* d_in, const int* in_sizes, int n_in,
                              void* d_out, int out_size) {
    const float* x   = (const float*)d_in[0];
    const float* Wq  = (const float*)d_in[1];
    const float* Wk  = (const float*)d_in[2];
    const float* Wv  = (const float*)d_in[3];
    const float* Wo  = (const float*)d_in[4];
    const float* lq1 = (const float*)d_in[5];
    const float* lk1 = (const float*)d_in[6];
    const float* lq2 = (const float*)d_in[7];
    const float* lk2 = (const float*)d_in[8];
    float* out = (float*)d_out;

    float *q_p, *k_p, *v_p, *oj_p, *att_p;
    cudaGetSymbolAddress((void**)&q_p,   g_q);
    cudaGetSymbolAddress((void**)&k_p,   g_k);
    cudaGetSymbolAddress((void**)&v_p,   g_v);
    cudaGetSymbolAddress((void**)&oj_p,  g_oj);
    cudaGetSymbolAddress((void**)&att_p, g_att);

    cudaFuncSetAttribute(flash_mma_kernel, cudaFuncAttributeMaxDynamicSharedMemorySize,
                         FLASH_SMEM_BYTES);

    lambda_kernel<<<1, 32>>>(lq1, lk1, lq2, lk2);

    dim3 ggrid(DIMN / 128, M_TOT / 128);
    gemm_tf32<<<ggrid, 256>>>(x, Wq, q_p, M_TOT, DIMN, DIMN, 0.125f);  // hd^-0.5
    gemm_tf32<<<ggrid, 256>>>(x, Wk, k_p, M_TOT, DIMN, DIMN, 1.0f);
    gemm_tf32<<<ggrid, 256>>>(x, Wv, v_p, M_TOT, DIMN, DIMN, 1.0f);

    dim3 fgrid(S_LEN / 128, NHEAD, BATCH);
    flash_mma_kernel<<<fgrid, 256, FLASH_SMEM_BYTES>>>(q_p, k_p, v_p, oj_p);

    combine_kernel<<<BATCH * S_LEN * 8, 128>>>(oj_p, att_p);

    gemm_tf32<<<ggrid, 256>>>(att_p, Wo, out, M_TOT, DIMN, DIMN, 1.0f);
}

// round 15
// speedup vs baseline: 1.4476x; 1.4476x over previous
#include <cuda_runtime.h>
#include <math.h>
#include <stdint.h>

#define DIMN   1024
#define S_LEN  2048
#define BATCH  2
#define NHEAD  16     // 2H attention heads (q/k), dim 64
#define HD     64
#define VD     128    // v head dim (2*hd)
#define M_TOT  (BATCH*S_LEN)   // 4096

#define LAMBDA_INIT 0.70082066706704805f

// ---------------- scratch (static device memory; no runtime allocs) ----------
__device__ float g_q[(size_t)BATCH*S_LEN*DIMN];
__device__ float g_k[(size_t)BATCH*S_LEN*DIMN];
__device__ float g_v[(size_t)BATCH*S_LEN*DIMN];
__device__ float g_oj[(size_t)BATCH*NHEAD*S_LEN*VD];   // per-attn-head O
__device__ float g_att[(size_t)BATCH*S_LEN*DIMN];      // combined, pre-Wo
__device__ float g_lambda;

// ---------------- lambda ------------------------------------------------------
__global__ void lambda_kernel(const float* __restrict__ lq1, const float* __restrict__ lk1,
                              const float* __restrict__ lq2, const float* __restrict__ lk2) {
    if (threadIdx.x == 0) {
        float s1 = 0.f, s2 = 0.f;
        for (int i = 0; i < HD; i++) { s1 += lq1[i]*lk1[i]; s2 += lq2[i]*lk2[i]; }
        g_lambda = expf(s1) - expf(s2) + LAMBDA_INIT;
    }
}

// ---------------- tf32 mma helpers -------------------------------------------
__device__ __forceinline__ uint32_t f2tf32(float x) {
    uint32_t r;
    asm("cvt.rna.tf32.f32 %0, %1;" : "=r"(r) : "f"(x));
    return r;
}
__device__ __forceinline__ float tf32hi(float x) {
    return __uint_as_float(f2tf32(x));
}

__device__ __forceinline__ void mma_tf32(float* c,
                                         uint32_t a0, uint32_t a1, uint32_t a2, uint32_t a3,
                                         uint32_t b0, uint32_t b1) {
    asm volatile("mma.sync.aligned.m16n8k8.row.col.f32.tf32.tf32.f32 "
                 "{%0,%1,%2,%3}, {%4,%5,%6,%7}, {%8,%9}, {%0,%1,%2,%3};\n"
                 : "+f"(c[0]), "+f"(c[1]), "+f"(c[2]), "+f"(c[3])
                 : "r"(a0), "r"(a1), "r"(a2), "r"(a3), "r"(b0), "r"(b1));
}

// ---------------- NT GEMM via tensor cores (3xTF32, reg-prefetch, R7 shape) ---
// C[m,n] = alpha * sum_k A[m,k]*B[n,k].  BM=BN=128, BK=16, 256 threads (8 warps
// in 2(M)x4(N)); each warp owns a 64x32 tile = 4x4 grid of m16n8k8 mmas.
__global__ __launch_bounds__(256) void gemm_tf32(const float* __restrict__ A,
                                                 const float* __restrict__ B,
                                                 float* __restrict__ C,
                                                 int M, int N, int K, float alpha) {
    __shared__ float As[128][20];
    __shared__ float Bs[128][20];
    const int tid  = threadIdx.x;
    const int lane = tid & 31;
    const int w    = tid >> 5;
    const int warp_m = (w & 1) * 64;       // 0 or 64
    const int warp_n = (w >> 1) * 32;      // 0,32,64,96
    const int lr = lane >> 2;              // 0..7
    const int lc = lane & 3;               // 0..3
    const int bm0 = blockIdx.y * 128, bn0 = blockIdx.x * 128;

    // staging: each thread stages 2 float4 per matrix per k-tile
    const int ldr  = tid >> 2;             // 0..63
    const int ldr2 = ldr + 64;
    const int ldc  = (tid & 3) << 2;

    float acc[4][4][4];                    // [mt][nt][4]
#pragma unroll
    for (int i = 0; i < 4; i++)
#pragma unroll
        for (int j = 0; j < 4; j++)
#pragma unroll
            for (int r = 0; r < 4; r++) acc[i][j][r] = 0.f;

    // prefetch first k-tile into registers
    float4 ra0 = *(const float4*)&A[(size_t)(bm0 + ldr ) * K + ldc];
    float4 ra1 = *(const float4*)&A[(size_t)(bm0 + ldr2) * K + ldc];
    float4 rb0 = *(const float4*)&B[(size_t)(bn0 + ldr ) * K + ldc];
    float4 rb1 = *(const float4*)&B[(size_t)(bn0 + ldr2) * K + ldc];

    for (int k0 = 0; k0 < K; k0 += 16) {
        *(float4*)&As[ldr ][ldc] = ra0;
        *(float4*)&As[ldr2][ldc] = ra1;
        *(float4*)&Bs[ldr ][ldc] = rb0;
        *(float4*)&Bs[ldr2][ldc] = rb1;
        __syncthreads();

        if (k0 + 16 < K) {
            int kn = k0 + 16;
            ra0 = *(const float4*)&A[(size_t)(bm0 + ldr ) * K + kn + ldc];
            ra1 = *(const float4*)&A[(size_t)(bm0 + ldr2) * K + kn + ldc];
            rb0 = *(const float4*)&B[(size_t)(bn0 + ldr ) * K + kn + ldc];
            rb1 = *(const float4*)&B[(size_t)(bn0 + ldr2) * K + kn + ldc];
        }

#pragma unroll
        for (int ks = 0; ks < 16; ks += 8) {
            // B fragments for all 4 nt tiles: b0 at (k=lc, n=lr), b1 at (k=lc+4, n=lr)
            uint32_t bh[4][2], bl[4][2];
#pragma unroll
            for (int nt = 0; nt < 4; nt++) {
                float b0 = Bs[warp_n + nt * 8 + lr][ks + lc];
                float b1 = Bs[warp_n + nt * 8 + lr][ks + lc + 4];
                bh[nt][0] = f2tf32(b0); bl[nt][0] = __float_as_uint(b0 - __uint_as_float(bh[nt][0]));
                bh[nt][1] = f2tf32(b1); bl[nt][1] = __float_as_uint(b1 - __uint_as_float(bh[nt][1]));
            }
#pragma unroll
            for (int mt = 0; mt < 4; mt++) {
                int r0 = warp_m + mt * 16 + lr;
                float a0 = As[r0    ][ks + lc];
                float a1 = As[r0 + 8][ks + lc];
                float a2 = As[r0    ][ks + lc + 4];
                float a3 = As[r0 + 8][ks + lc + 4];
                uint32_t ah0 = f2tf32(a0), ah1 = f2tf32(a1), ah2 = f2tf32(a2), ah3 = f2tf32(a3);
                uint32_t al0 = __float_as_uint(a0 - __uint_as_float(ah0));
                uint32_t al1 = __float_as_uint(a1 - __uint_as_float(ah1));
                uint32_t al2 = __float_as_uint(a2 - __uint_as_float(ah2));
                uint32_t al3 = __float_as_uint(a3 - __uint_as_float(ah3));
#pragma unroll
                for (int nt = 0; nt < 4; nt++) {
                    mma_tf32(acc[mt][nt], ah0, ah1, ah2, ah3, bh[nt][0], bh[nt][1]);
                    mma_tf32(acc[mt][nt], ah0, ah1, ah2, ah3, bl[nt][0], bl[nt][1]);
                    mma_tf32(acc[mt][nt], al0, al1, al2, al3, bh[nt][0], bh[nt][1]);
                }
            }
        }
        __syncthreads();
    }

    // epilogue: c0,c1 at (row lr, col lc*2 +0/1), c2,c3 at (row lr+8, ...)
#pragma unroll
    for (int mt = 0; mt < 4; mt++) {
#pragma unroll
        for (int nt = 0; nt < 4; nt++) {
            int row = bm0 + warp_m + mt * 16 + lr;
            int col = bn0 + warp_n + nt * 8 + lc * 2;
            float2 lo = make_float2(alpha * acc[mt][nt][0], alpha * acc[mt][nt][1]);
            float2 hi = make_float2(alpha * acc[mt][nt][2], alpha * acc[mt][nt][3]);
            *(float2*)&C[(size_t)row * N + col]       = lo;
            *(float2*)&C[(size_t)(row + 8) * N + col] = hi;
        }
    }
}

// ---------------- flash attention, tensor-core version ------------------------
// BM=128 q rows, BN=64 keys/iter, hd=64, VD=128. 256 threads = 8 warps, each
// warp owns 16 q rows (softmax state warp-local). QK = 3xTF32, PV = 1xTF32.
// smem floats: Qh/Ql 128x68, Kh/Kl 64x68, V 64x136, P 128x68  -> 174080 B
#define FL_QS 68
#define FL_VS 136
#define FLASH_SMEM_FLOATS (2*128*FL_QS + 2*64*FL_QS + 64*FL_VS + 128*FL_QS)
#define FLASH_SMEM_BYTES  (FLASH_SMEM_FLOATS * 4)

__global__ __launch_bounds__(256, 1) void flash_mma_kernel(const float* __restrict__ q,
                                                           const float* __restrict__ k,
                                                           const float* __restrict__ v,
                                                           float* __restrict__ oj) {
    extern __shared__ float sm[];
    float (*Qh)[FL_QS] = (float (*)[FL_QS])sm;
    float (*Ql)[FL_QS] = (float (*)[FL_QS])(sm + 128 * FL_QS);
    float (*Kh)[FL_QS] = (float (*)[FL_QS])(sm + 2 * 128 * FL_QS);
    float (*Kl)[FL_QS] = (float (*)[FL_QS])(sm + 2 * 128 * FL_QS + 64 * FL_QS);
    float (*Vs)[FL_VS] = (float (*)[FL_VS])(sm + 2 * 128 * FL_QS + 2 * 64 * FL_QS);
    float (*Ps)[FL_QS] = (float (*)[FL_QS])(sm + 2 * 128 * FL_QS + 2 * 64 * FL_QS + 64 * FL_VS);

    const int tid  = threadIdx.x;
    const int lane = tid & 31;
    const int w    = tid >> 5;
    const int wm   = w * 16;               // warp's 16 q rows
    const int lr   = lane >> 2;            // 0..7
    const int lc   = lane & 3;             // 0..3
    const int qb   = (gridDim.x - 1) - blockIdx.x;   // big tiles first
    const int h    = blockIdx.y;
    const int b    = blockIdx.z;
    const int hv   = h >> 1;

    const float* qbase = q + ((size_t)(b * S_LEN + qb * 128)) * DIMN + h * HD;
    const float* kbase = k + (size_t)b * S_LEN * DIMN + h * HD;
    const float* vbase = v + (size_t)b * S_LEN * DIMN + hv * VD;

    // load Q tile 128x64, split hi/lo. 2048 float4, 8 per thread.
#pragma unroll
    for (int u = 0; u < 8; u++) {
        int idx = tid + u * 256;
        int row = idx >> 4;
        int c4  = (idx & 15) << 2;
        float4 x = *(const float4*)&qbase[(size_t)row * DIMN + c4];
        float4 hh, ll;
        hh.x=tf32hi(x.x); hh.y=tf32hi(x.y); hh.z=tf32hi(x.z); hh.w=tf32hi(x.w);
        ll.x=x.x-hh.x; ll.y=x.y-hh.y; ll.z=x.z-hh.z; ll.w=x.w-hh.w;
        *(float4*)&Qh[row][c4] = hh;
        *(float4*)&Ql[row][c4] = ll;
    }

    float mrow[2], lrow[2];
    float o[16][4];
    mrow[0] = mrow[1] = -1e30f;
    lrow[0] = lrow[1] = 0.f;
#pragma unroll
    for (int i = 0; i < 16; i++)
#pragma unroll
        for (int r = 0; r < 4; r++) o[i][r] = 0.f;

    const int ktiles = 2 * qb + 2;
    for (int kt = 0; kt < ktiles; kt++) {
        __syncthreads();
        // load K tile 64x64 (split hi/lo): 1024 float4, 4/thread
#pragma unroll
        for (int u = 0; u < 4; u++) {
            int idx = tid + u * 256;
            int row = idx >> 4;
            int c4  = (idx & 15) << 2;
            float4 x = *(const float4*)&kbase[(size_t)(kt * 64 + row) * DIMN + c4];
            float4 hh, ll;
            hh.x=tf32hi(x.x); hh.y=tf32hi(x.y); hh.z=tf32hi(x.z); hh.w=tf32hi(x.w);
            ll.x=x.x-hh.x; ll.y=x.y-hh.y; ll.z=x.z-hh.z; ll.w=x.w-hh.w;
            *(float4*)&Kh[row][c4] = hh;
            *(float4*)&Kl[row][c4] = ll;
        }
        // load V tile 64x128 (tf32-rounded): 2048 float4, 8/thread
#pragma unroll
        for (int u = 0; u < 8; u++) {
            int idx = tid + u * 256;
            int row = idx >> 5;
            int c4  = (idx & 31) << 2;
            float4 x = *(const float4*)&vbase[(size_t)(kt * 64 + row) * DIMN + c4];
            x.x=tf32hi(x.x); x.y=tf32hi(x.y); x.z=tf32hi(x.z); x.w=tf32hi(x.w);
            *(float4*)&Vs[row][c4] = x;
        }
        __syncthreads();

        // ---- S = Q K^T via 3xTF32: 8 n8-tiles x 8 k-steps ----
        float s[8][4];
#pragma unroll
        for (int nt = 0; nt < 8; nt++)
#pragma unroll
            for (int r = 0; r < 4; r++) s[nt][r] = 0.f;

#pragma unroll
        for (int ks = 0; ks < 64; ks += 8) {
            int r0 = wm + lr;
            uint32_t ah0 = __float_as_uint(Qh[r0    ][ks + lc]);
            uint32_t ah1 = __float_as_uint(Qh[r0 + 8][ks + lc]);
            uint32_t ah2 = __float_as_uint(Qh[r0    ][ks + lc + 4]);
            uint32_t ah3 = __float_as_uint(Qh[r0 + 8][ks + lc + 4]);
            uint32_t al0 = __float_as_uint(Ql[r0    ][ks + lc]);
            uint32_t al1 = __float_as_uint(Ql[r0 + 8][ks + lc]);
            uint32_t al2 = __float_as_uint(Ql[r0    ][ks + lc + 4]);
            uint32_t al3 = __float_as_uint(Ql[r0 + 8][ks + lc + 4]);
#pragma unroll
            for (int nt = 0; nt < 8; nt++) {
                int rn = nt * 8 + lr;
                uint32_t bh0 = __float_as_uint(Kh[rn][ks + lc]);
                uint32_t bh1 = __float_as_uint(Kh[rn][ks + lc + 4]);
                uint32_t bl0 = __float_as_uint(Kl[rn][ks + lc]);
                uint32_t bl1 = __float_as_uint(Kl[rn][ks + lc + 4]);
                mma_tf32(s[nt], ah0, ah1, ah2, ah3, bh0, bh1);
                mma_tf32(s[nt], ah0, ah1, ah2, ah3, bl0, bl1);
                mma_tf32(s[nt], al0, al1, al2, al3, bh0, bh1);
            }
        }

        // ---- causal mask on diagonal tiles ----
        if (kt >= 2 * qb) {
            int koff = kt * 64 - qb * 128;   // 0 or 64
            int r0 = wm + lr, r1 = wm + lr + 8;
#pragma unroll
            for (int nt = 0; nt < 8; nt++) {
                int c0 = koff + nt * 8 + lc * 2;
                int c1 = c0 + 1;
                if (c0 > r0) s[nt][0] = -1e30f;
                if (c1 > r0) s[nt][1] = -1e30f;
                if (c0 > r1) s[nt][2] = -1e30f;
                if (c1 > r1) s[nt][3] = -1e30f;
            }
        }

        // ---- online softmax (rows lr and lr+8, quad-wide reductions) ----
#pragma unroll
        for (int half = 0; half < 2; half++) {
            float mt = -1e30f;
#pragma unroll
            for (int nt = 0; nt < 8; nt++)
                mt = fmaxf(mt, fmaxf(s[nt][2*half], s[nt][2*half+1]));
            mt = fmaxf(mt, __shfl_xor_sync(0xffffffffu, mt, 1));
            mt = fmaxf(mt, __shfl_xor_sync(0xffffffffu, mt, 2));
            float mn = fmaxf(mrow[half], mt);
            float sc = __expf(mrow[half] - mn);
            float ps = 0.f;
#pragma unroll
            for (int nt = 0; nt < 8; nt++) {
                float e0 = __expf(s[nt][2*half]   - mn);
                float e1 = __expf(s[nt][2*half+1] - mn);
                ps += e0 + e1;
                s[nt][2*half]   = e0;
                s[nt][2*half+1] = e1;
            }
            ps += __shfl_xor_sync(0xffffffffu, ps, 1);
            ps += __shfl_xor_sync(0xffffffffu, ps, 2);
            lrow[half] = lrow[half] * sc + ps;
            mrow[half] = mn;
#pragma unroll
            for (int nt = 0; nt < 16; nt++) {
                o[nt][2*half]   *= sc;
                o[nt][2*half+1] *= sc;
            }
        }

        // ---- stage P (tf32-rounded) to this warp's smem rows ----
        {
            int r0 = wm + lr, r1 = wm + lr + 8;
#pragma unroll
            for (int nt = 0; nt < 8; nt++) {
                int c = nt * 8 + lc * 2;
                Ps[r0][c]     = tf32hi(s[nt][0]);
                Ps[r0][c + 1] = tf32hi(s[nt][1]);
                Ps[r1][c]     = tf32hi(s[nt][2]);
                Ps[r1][c + 1] = tf32hi(s[nt][3]);
            }
        }
        __syncwarp();

        // ---- O += P @ V : 16 vd n8-tiles x 8 k-steps ----
#pragma unroll
        for (int ks = 0; ks < 64; ks += 8) {
            int r0 = wm + lr;
            uint32_t a0 = __float_as_uint(Ps[r0    ][ks + lc]);
            uint32_t a1 = __float_as_uint(Ps[r0 + 8][ks + lc]);
            uint32_t a2 = __float_as_uint(Ps[r0    ][ks + lc + 4]);
            uint32_t a3 = __float_as_uint(Ps[r0 + 8][ks + lc + 4]);
#pragma unroll
            for (int nt = 0; nt < 16; nt++) {
                uint32_t b0 = __float_as_uint(Vs[ks + lc    ][nt * 8 + lr]);
                uint32_t b1 = __float_as_uint(Vs[ks + lc + 4][nt * 8 + lr]);
                mma_tf32(o[nt], a0, a1, a2, a3, b0, b1);
            }
        }
    }

    // ---- epilogue: O /= l, store ----
    float* obase = oj + (((size_t)(b * NHEAD + h)) * S_LEN + qb * 128) * VD;
    float inv0 = 1.f / lrow[0];
    float inv1 = 1.f / lrow[1];
    int r0 = wm + lr, r1 = wm + lr + 8;
#pragma unroll
    for (int nt = 0; nt < 16; nt++) {
        int c = nt * 8 + lc * 2;
        *(float2*)&obase[(size_t)r0 * VD + c] = make_float2(o[nt][0] * inv0, o[nt][1] * inv0);
        *(float2*)&obase[(size_t)r1 * VD + c] = make_float2(o[nt][2] * inv1, o[nt][3] * inv1);
    }
}

// ---------------- combine pairs + RMSNorm -------------------------------------
__global__ void combine_kernel(const float* __restrict__ oj, float* __restrict__ att) {
    const int bid = blockIdx.x;
    const int hv = bid & 7;
    const int s  = (bid >> 3) & (S_LEN - 1);
    const int b  = bid >> 14;
    const int d  = threadIdx.x;

    const float lam = g_lambda;
    size_t i0 = (((size_t)(b * NHEAD + 2 * hv)) * S_LEN + s) * VD + d;
    size_t i1 = i0 + (size_t)S_LEN * VD;
    float val = oj[i0] - lam * oj[i1];

    float v2 = val * val;
#pragma unroll
    for (int off = 16; off > 0; off >>= 1)
        v2 += __shfl_xor_sync(0xffffffffu, v2, off);
    __shared__ float red[4];
    if ((d & 31) == 0) red[d >> 5] = v2;
    __syncthreads();
    float tot = red[0] + red[1] + red[2] + red[3];
    float rms = rsqrtf(tot * (1.0f / 128.0f) + 1e-5f);
    att[((size_t)(b * S_LEN) + s) * DIMN + hv * VD + d] = val * rms * (1.0f - LAMBDA_INIT);
}

// ---------------- launch ------------------------------------------------------
extern "C" void kernel_launch(void* const* d_in, const int* in_sizes, int n_in,
                              void* d_out, int out_size) {
    const float* x   = (const float*)d_in[0];
    const float* Wq  = (const float*)d_in[1];
    const float* Wk  = (const float*)d_in[2];
    const float* Wv  = (const float*)d_in[3];
    const float* Wo  = (const float*)d_in[4];
    const float* lq1 = (const float*)d_in[5];
    const float* lk1 = (const float*)d_in[6];
    const float* lq2 = (const float*)d_in[7];
    const float* lk2 = (const float*)d_in[8];
    float* out = (float*)d_out;

    float *q_p, *k_p, *v_p, *oj_p, *att_p;
    cudaGetSymbolAddress((void**)&q_p,   g_q);
    cudaGetSymbolAddress((void**)&k_p,   g_k);
    cudaGetSymbolAddress((void**)&v_p,   g_v);
    cudaGetSymbolAddress((void**)&oj_p,  g_oj);
    cudaGetSymbolAddress((void**)&att_p, g_att);

    cudaFuncSetAttribute(flash_mma_kernel, cudaFuncAttributeMaxDynamicSharedMemorySize,
                         FLASH_SMEM_BYTES);

    lambda_kernel<<<1, 32>>>(lq1, lk1, lq2, lk2);

    dim3 ggrid(DIMN / 128, M_TOT / 128);
    gemm_tf32<<<ggrid, 256>>>(x, Wq, q_p, M_TOT, DIMN, DIMN, 0.125f);  // hd^-0.5
    gemm_tf32<<<ggrid, 256>>>(x, Wk, k_p, M_TOT, DIMN, DIMN, 1.0f);
    gemm_tf32<<<ggrid, 256>>>(x, Wv, v_p, M_TOT, DIMN, DIMN, 1.0f);

    dim3 fgrid(S_LEN / 128, NHEAD, BATCH);
    flash_mma_kernel<<<fgrid, 256, FLASH_SMEM_BYTES>>>(q_p, k_p, v_p, oj_p);

    combine_kernel<<<BATCH * S_LEN * 8, 128>>>(oj_p, att_p);

    gemm_tf32<<<ggrid, 256>>>(att_p, Wo, out, M_TOT, DIMN, DIMN, 1.0f);
}

// round 16
// speedup vs baseline: 2.2902x; 1.5821x over previous
#include <cuda_runtime.h>
#include <cuda_bf16.h>
#include <math.h>
#include <stdint.h>

#define DIMN   1024
#define S_LEN  2048
#define BATCH  2
#define NHEAD  16     // 2H attention heads (q/k), dim 64
#define HD     64
#define VD     128    // v head dim (2*hd)
#define M_TOT  (BATCH*S_LEN)   // 4096

#define LAMBDA_INIT 0.70082066706704805f

// ---------------- scratch (static device memory; no runtime allocs) ----------
__device__ float g_q[(size_t)BATCH*S_LEN*DIMN];
__device__ float g_k[(size_t)BATCH*S_LEN*DIMN];
__device__ float g_v[(size_t)BATCH*S_LEN*DIMN];
__device__ float g_oj[(size_t)BATCH*NHEAD*S_LEN*VD];   // per-attn-head O
__device__ float g_att[(size_t)BATCH*S_LEN*DIMN];      // combined, pre-Wo
__device__ float g_lambda;

// ---------------- lambda ------------------------------------------------------
__global__ void lambda_kernel(const float* __restrict__ lq1, const float* __restrict__ lk1,
                              const float* __restrict__ lq2, const float* __restrict__ lk2) {
    if (threadIdx.x == 0) {
        float s1 = 0.f, s2 = 0.f;
        for (int i = 0; i < HD; i++) { s1 += lq1[i]*lk1[i]; s2 += lq2[i]*lk2[i]; }
        g_lambda = expf(s1) - expf(s2) + LAMBDA_INIT;
    }
}

// ---------------- mma helpers -------------------------------------------------
__device__ __forceinline__ uint32_t f2tf32(float x) {
    uint32_t r;
    asm("cvt.rna.tf32.f32 %0, %1;" : "=r"(r) : "f"(x));
    return r;
}
__device__ __forceinline__ float tf32hi(float x) {
    return __uint_as_float(f2tf32(x));
}

__device__ __forceinline__ void mma_tf32(float* c,
                                         uint32_t a0, uint32_t a1, uint32_t a2, uint32_t a3,
                                         uint32_t b0, uint32_t b1) {
    asm volatile("mma.sync.aligned.m16n8k8.row.col.f32.tf32.tf32.f32 "
                 "{%0,%1,%2,%3}, {%4,%5,%6,%7}, {%8,%9}, {%0,%1,%2,%3};\n"
                 : "+f"(c[0]), "+f"(c[1]), "+f"(c[2]), "+f"(c[3])
                 : "r"(a0), "r"(a1), "r"(a2), "r"(a3), "r"(b0), "r"(b1));
}

__device__ __forceinline__ void mma_bf16(float* c,
                                         uint32_t a0, uint32_t a1, uint32_t a2, uint32_t a3,
                                         uint32_t b0, uint32_t b1) {
    asm volatile("mma.sync.aligned.m16n8k16.row.col.f32.bf16.bf16.f32 "
                 "{%0,%1,%2,%3}, {%4,%5,%6,%7}, {%8,%9}, {%0,%1,%2,%3};\n"
                 : "+f"(c[0]), "+f"(c[1]), "+f"(c[2]), "+f"(c[3])
                 : "r"(a0), "r"(a1), "r"(a2), "r"(a3), "r"(b0), "r"(b1));
}

// split float2 -> packed bf16x2 hi + lo  (low 16 bits = first element)
__device__ __forceinline__ void split2bf16(float x, float y, uint32_t& hi, uint32_t& lo) {
    __nv_bfloat162 h = __floats2bfloat162_rn(x, y);
    float2 hf = __bfloat1622float2(h);
    __nv_bfloat162 l = __floats2bfloat162_rn(x - hf.x, y - hf.y);
    hi = *(uint32_t*)&h;
    lo = *(uint32_t*)&l;
}

// ---------------- NT GEMM via bf16-3x tensor cores ----------------------------
// C[m,n] = alpha * sum_k A[m,k]*B[n,k].  BM=BN=128, BK=16, 256 threads (8 warps
// in 2(M)x4(N)); each warp owns 64x32 = 4x4 grid of m16n8k16 mmas (3 per k16).
// Up to 3 B/C matrices in one launch (shared A): sel = blockIdx.x>>3.
__global__ __launch_bounds__(256) void gemm_bf16x3(const float* __restrict__ A,
                                                   const float* __restrict__ B0,
                                                   const float* __restrict__ B1,
                                                   const float* __restrict__ B2,
                                                   float* __restrict__ C0,
                                                   float* __restrict__ C1,
                                                   float* __restrict__ C2,
                                                   int M, int N, int K,
                                                   float al0, float al1, float al2) {
    // packed bf16x2 tiles: 8 used pair-cols + 4 pad -> stride 12 (conflict-free frags)
    __shared__ uint32_t Ah[128][12], Al[128][12];
    __shared__ uint32_t Bh[128][12], Bl[128][12];

    const int sel = blockIdx.x >> 3;
    const float* B = (sel == 0) ? B0 : (sel == 1) ? B1 : B2;
    float*       C = (sel == 0) ? C0 : (sel == 1) ? C1 : C2;
    const float alpha = (sel == 0) ? al0 : (sel == 1) ? al1 : al2;

    const int tid  = threadIdx.x;
    const int lane = tid & 31;
    const int w    = tid >> 5;
    const int warp_m = (w & 1) * 64;
    const int warp_n = (w >> 1) * 32;
    const int lr = lane >> 2;              // 0..7
    const int lc = lane & 3;               // 0..3
    const int bm0 = blockIdx.y * 128, bn0 = (blockIdx.x & 7) * 128;

    const int ldr  = tid >> 2;             // 0..63
    const int ldr2 = ldr + 64;
    const int pc   = (tid & 3) << 1;       // pair-col base (0,2,4,6)
    const int ldc  = (tid & 3) << 2;       // float col base

    float acc[4][4][4];
#pragma unroll
    for (int i = 0; i < 4; i++)
#pragma unroll
        for (int j = 0; j < 4; j++)
#pragma unroll
            for (int r = 0; r < 4; r++) acc[i][j][r] = 0.f;

    // prefetch first k-tile into registers
    float4 ra0 = *(const float4*)&A[(size_t)(bm0 + ldr ) * K + ldc];
    float4 ra1 = *(const float4*)&A[(size_t)(bm0 + ldr2) * K + ldc];
    float4 rb0 = *(const float4*)&B[(size_t)(bn0 + ldr ) * K + ldc];
    float4 rb1 = *(const float4*)&B[(size_t)(bn0 + ldr2) * K + ldc];

    for (int k0 = 0; k0 < K; k0 += 16) {
        // split + commit staged registers to smem (packed bf16x2)
        {
            uint32_t h0, l0, h1, l1;
            split2bf16(ra0.x, ra0.y, h0, l0); split2bf16(ra0.z, ra0.w, h1, l1);
            Ah[ldr ][pc] = h0; Ah[ldr ][pc+1] = h1; Al[ldr ][pc] = l0; Al[ldr ][pc+1] = l1;
            split2bf16(ra1.x, ra1.y, h0, l0); split2bf16(ra1.z, ra1.w, h1, l1);
            Ah[ldr2][pc] = h0; Ah[ldr2][pc+1] = h1; Al[ldr2][pc] = l0; Al[ldr2][pc+1] = l1;
            split2bf16(rb0.x, rb0.y, h0, l0); split2bf16(rb0.z, rb0.w, h1, l1);
            Bh[ldr ][pc] = h0; Bh[ldr ][pc+1] = h1; Bl[ldr ][pc] = l0; Bl[ldr ][pc+1] = l1;
            split2bf16(rb1.x, rb1.y, h0, l0); split2bf16(rb1.z, rb1.w, h1, l1);
            Bh[ldr2][pc] = h0; Bh[ldr2][pc+1] = h1; Bl[ldr2][pc] = l0; Bl[ldr2][pc+1] = l1;
        }
        __syncthreads();

        // issue next tile's global loads (overlap with mma body)
        if (k0 + 16 < K) {
            int kn = k0 + 16;
            ra0 = *(const float4*)&A[(size_t)(bm0 + ldr ) * K + kn + ldc];
            ra1 = *(const float4*)&A[(size_t)(bm0 + ldr2) * K + kn + ldc];
            rb0 = *(const float4*)&B[(size_t)(bn0 + ldr ) * K + kn + ldc];
            rb1 = *(const float4*)&B[(size_t)(bn0 + ldr2) * K + kn + ldc];
        }

        // one k16 step per tile
        {
            uint32_t bh[4][2], bl[4][2];
#pragma unroll
            for (int nt = 0; nt < 4; nt++) {
                int rn = warp_n + nt * 8 + lr;
                bh[nt][0] = Bh[rn][lc];     bh[nt][1] = Bh[rn][lc + 4];
                bl[nt][0] = Bl[rn][lc];     bl[nt][1] = Bl[rn][lc + 4];
            }
#pragma unroll
            for (int mt = 0; mt < 4; mt++) {
                int r0 = warp_m + mt * 16 + lr;
                uint32_t ah0 = Ah[r0    ][lc];
                uint32_t ah1 = Ah[r0 + 8][lc];
                uint32_t ah2 = Ah[r0    ][lc + 4];
                uint32_t ah3 = Ah[r0 + 8][lc + 4];
                uint32_t al0 = Al[r0    ][lc];
                uint32_t al1 = Al[r0 + 8][lc];
                uint32_t al2 = Al[r0    ][lc + 4];
                uint32_t al3 = Al[r0 + 8][lc + 4];
#pragma unroll
                for (int nt = 0; nt < 4; nt++) {
                    mma_bf16(acc[mt][nt], ah0, ah1, ah2, ah3, bh[nt][0], bh[nt][1]);
                    mma_bf16(acc[mt][nt], ah0, ah1, ah2, ah3, bl[nt][0], bl[nt][1]);
                    mma_bf16(acc[mt][nt], al0, al1, al2, al3, bh[nt][0], bh[nt][1]);
                }
            }
        }
        __syncthreads();
    }

    // epilogue: c0,c1 at (row lr, col lc*2 +0/1), c2,c3 at (row lr+8, ...)
#pragma unroll
    for (int mt = 0; mt < 4; mt++) {
#pragma unroll
        for (int nt = 0; nt < 4; nt++) {
            int row = bm0 + warp_m + mt * 16 + lr;
            int col = bn0 + warp_n + nt * 8 + lc * 2;
            float2 lo = make_float2(alpha * acc[mt][nt][0], alpha * acc[mt][nt][1]);
            float2 hi = make_float2(alpha * acc[mt][nt][2], alpha * acc[mt][nt][3]);
            *(float2*)&C[(size_t)row * N + col]       = lo;
            *(float2*)&C[(size_t)(row + 8) * N + col] = hi;
        }
    }
}

// ---------------- flash attention, tensor-core version ------------------------
// BM=128 q rows, BN=64 keys/iter, hd=64, VD=128. 256 threads = 8 warps, each
// warp owns 16 q rows (softmax state warp-local). QK = bf16-3x (m16n8k16),
// PV = 1xTF32 (m16n8k8).
// smem: Qh/Ql u32[128][36], Kh/Kl u32[64][36], V f32[64][136], P f32[128][68]
#define FL_QP 36       // pair stride for Q/K (16 pairs used + pad; 4r+c bank map)
#define FL_VS 136
#define FL_PS 68
#define OFF_QH 0
#define OFF_QL (OFF_QH + 128*FL_QP)
#define OFF_KH (OFF_QL + 128*FL_QP)
#define OFF_KL (OFF_KH + 64*FL_QP)
#define OFF_V  (OFF_KL + 64*FL_QP)
#define OFF_P  (OFF_V  + 64*FL_VS)
#define FLASH_SMEM_WORDS (OFF_P + 128*FL_PS)
#define FLASH_SMEM_BYTES (FLASH_SMEM_WORDS * 4)

__global__ __launch_bounds__(256, 1) void flash_mma_kernel(const float* __restrict__ q,
                                                           const float* __restrict__ k,
                                                           const float* __restrict__ v,
                                                           float* __restrict__ oj) {
    extern __shared__ uint32_t smw[];
    uint32_t (*Qh)[FL_QP] = (uint32_t (*)[FL_QP])(smw + OFF_QH);
    uint32_t (*Ql)[FL_QP] = (uint32_t (*)[FL_QP])(smw + OFF_QL);
    uint32_t (*Kh)[FL_QP] = (uint32_t (*)[FL_QP])(smw + OFF_KH);
    uint32_t (*Kl)[FL_QP] = (uint32_t (*)[FL_QP])(smw + OFF_KL);
    float    (*Vs)[FL_VS] = (float    (*)[FL_VS])(smw + OFF_V);
    float    (*Ps)[FL_PS] = (float    (*)[FL_PS])(smw + OFF_P);

    const int tid  = threadIdx.x;
    const int lane = tid & 31;
    const int w    = tid >> 5;
    const int wm   = w * 16;               // warp's 16 q rows
    const int lr   = lane >> 2;            // 0..7
    const int lc   = lane & 3;             // 0..3
    const int qb   = (gridDim.x - 1) - blockIdx.x;   // big tiles first
    const int h    = blockIdx.y;
    const int b    = blockIdx.z;
    const int hv   = h >> 1;

    const float* qbase = q + ((size_t)(b * S_LEN + qb * 128)) * DIMN + h * HD;
    const float* kbase = k + (size_t)b * S_LEN * DIMN + h * HD;
    const float* vbase = v + (size_t)b * S_LEN * DIMN + hv * VD;

    // load Q tile 128x64, bf16 split. 2048 float4, 8 per thread.
#pragma unroll
    for (int u = 0; u < 8; u++) {
        int idx = tid + u * 256;
        int row = idx >> 4;
        int c4  = (idx & 15) << 2;
        int pb  = (idx & 15) << 1;
        float4 x = *(const float4*)&qbase[(size_t)row * DIMN + c4];
        uint32_t h0, l0, h1, l1;
        split2bf16(x.x, x.y, h0, l0);
        split2bf16(x.z, x.w, h1, l1);
        Qh[row][pb] = h0; Qh[row][pb + 1] = h1;
        Ql[row][pb] = l0; Ql[row][pb + 1] = l1;
    }

    float mrow[2], lrow[2];
    float o[16][4];
    mrow[0] = mrow[1] = -1e30f;
    lrow[0] = lrow[1] = 0.f;
#pragma unroll
    for (int i = 0; i < 16; i++)
#pragma unroll
        for (int r = 0; r < 4; r++) o[i][r] = 0.f;

    const int ktiles = 2 * qb + 2;
    for (int kt = 0; kt < ktiles; kt++) {
        __syncthreads();
        // load K tile 64x64 (bf16 split): 1024 float4, 4/thread
#pragma unroll
        for (int u = 0; u < 4; u++) {
            int idx = tid + u * 256;
            int row = idx >> 4;
            int c4  = (idx & 15) << 2;
            int pb  = (idx & 15) << 1;
            float4 x = *(const float4*)&kbase[(size_t)(kt * 64 + row) * DIMN + c4];
            uint32_t h0, l0, h1, l1;
            split2bf16(x.x, x.y, h0, l0);
            split2bf16(x.z, x.w, h1, l1);
            Kh[row][pb] = h0; Kh[row][pb + 1] = h1;
            Kl[row][pb] = l0; Kl[row][pb + 1] = l1;
        }
        // load V tile 64x128 (tf32-rounded): 2048 float4, 8/thread
#pragma unroll
        for (int u = 0; u < 8; u++) {
            int idx = tid + u * 256;
            int row = idx >> 5;
            int c4  = (idx & 31) << 2;
            float4 x = *(const float4*)&vbase[(size_t)(kt * 64 + row) * DIMN + c4];
            x.x=tf32hi(x.x); x.y=tf32hi(x.y); x.z=tf32hi(x.z); x.w=tf32hi(x.w);
            *(float4*)&Vs[row][c4] = x;
        }
        __syncthreads();

        // ---- S = Q K^T via bf16-3x: 8 n8-tiles x 4 k16-steps ----
        float s[8][4];
#pragma unroll
        for (int nt = 0; nt < 8; nt++)
#pragma unroll
            for (int r = 0; r < 4; r++) s[nt][r] = 0.f;

#pragma unroll
        for (int ks = 0; ks < 4; ks++) {
            int r0 = wm + lr;
            int p0 = 8 * ks + lc, p1 = p0 + 4;
            uint32_t ah0 = Qh[r0    ][p0];
            uint32_t ah1 = Qh[r0 + 8][p0];
            uint32_t ah2 = Qh[r0    ][p1];
            uint32_t ah3 = Qh[r0 + 8][p1];
            uint32_t al0 = Ql[r0    ][p0];
            uint32_t al1 = Ql[r0 + 8][p0];
            uint32_t al2 = Ql[r0    ][p1];
            uint32_t al3 = Ql[r0 + 8][p1];
#pragma unroll
            for (int nt = 0; nt < 8; nt++) {
                int rn = nt * 8 + lr;
                uint32_t bh0 = Kh[rn][p0];
                uint32_t bh1 = Kh[rn][p1];
                uint32_t bl0 = Kl[rn][p0];
                uint32_t bl1 = Kl[rn][p1];
                mma_bf16(s[nt], ah0, ah1, ah2, ah3, bh0, bh1);
                mma_bf16(s[nt], ah0, ah1, ah2, ah3, bl0, bl1);
                mma_bf16(s[nt], al0, al1, al2, al3, bh0, bh1);
            }
        }

        // ---- causal mask on diagonal tiles ----
        if (kt >= 2 * qb) {
            int koff = kt * 64 - qb * 128;   // 0 or 64
            int r0 = wm + lr, r1 = wm + lr + 8;
#pragma unroll
            for (int nt = 0; nt < 8; nt++) {
                int c0 = koff + nt * 8 + lc * 2;
                int c1 = c0 + 1;
                if (c0 > r0) s[nt][0] = -1e30f;
                if (c1 > r0) s[nt][1] = -1e30f;
                if (c0 > r1) s[nt][2] = -1e30f;
                if (c1 > r1) s[nt][3] = -1e30f;
            }
        }

        // ---- online softmax (rows lr and lr+8, quad-wide reductions) ----
#pragma unroll
        for (int half = 0; half < 2; half++) {
            float mt = -1e30f;
#pragma unroll
            for (int nt = 0; nt < 8; nt++)
                mt = fmaxf(mt, fmaxf(s[nt][2*half], s[nt][2*half+1]));
            mt = fmaxf(mt, __shfl_xor_sync(0xffffffffu, mt, 1));
            mt = fmaxf(mt, __shfl_xor_sync(0xffffffffu, mt, 2));
            float mn = fmaxf(mrow[half], mt);
            float sc = __expf(mrow[half] - mn);
            float ps = 0.f;
#pragma unroll
            for (int nt = 0; nt < 8; nt++) {
                float e0 = __expf(s[nt][2*half]   - mn);
                float e1 = __expf(s[nt][2*half+1] - mn);
                ps += e0 + e1;
                s[nt][2*half]   = e0;
                s[nt][2*half+1] = e1;
            }
            ps += __shfl_xor_sync(0xffffffffu, ps, 1);
            ps += __shfl_xor_sync(0xffffffffu, ps, 2);
            lrow[half] = lrow[half] * sc + ps;
            mrow[half] = mn;
#pragma unroll
            for (int nt = 0; nt < 16; nt++) {
                o[nt][2*half]   *= sc;
                o[nt][2*half+1] *= sc;
            }
        }

        // ---- stage P (tf32-rounded) to this warp's smem rows ----
        {
            int r0 = wm + lr, r1 = wm + lr + 8;
#pragma unroll
            for (int nt = 0; nt < 8; nt++) {
                int c = nt * 8 + lc * 2;
                Ps[r0][c]     = tf32hi(s[nt][0]);
                Ps[r0][c + 1] = tf32hi(s[nt][1]);
                Ps[r1][c]     = tf32hi(s[nt][2]);
                Ps[r1][c + 1] = tf32hi(s[nt][3]);
            }
        }
        __syncwarp();

        // ---- O += P @ V : 16 vd n8-tiles x 8 k8-steps (tf32) ----
#pragma unroll
        for (int ks = 0; ks < 64; ks += 8) {
            int r0 = wm + lr;
            uint32_t a0 = __float_as_uint(Ps[r0    ][ks + lc]);
            uint32_t a1 = __float_as_uint(Ps[r0 + 8][ks + lc]);
            uint32_t a2 = __float_as_uint(Ps[r0    ][ks + lc + 4]);
            uint32_t a3 = __float_as_uint(Ps[r0 + 8][ks + lc + 4]);
#pragma unroll
            for (int nt = 0; nt < 16; nt++) {
                uint32_t b0 = __float_as_uint(Vs[ks + lc    ][nt * 8 + lr]);
                uint32_t b1 = __float_as_uint(Vs[ks + lc + 4][nt * 8 + lr]);
                mma_tf32(o[nt], a0, a1, a2, a3, b0, b1);
            }
        }
    }

    // ---- epilogue: O /= l, store ----
    float* obase = oj + (((size_t)(b * NHEAD + h)) * S_LEN + qb * 128) * VD;
    float inv0 = 1.f / lrow[0];
    float inv1 = 1.f / lrow[1];
    int r0 = wm + lr, r1 = wm + lr + 8;
#pragma unroll
    for (int nt = 0; nt < 16; nt++) {
        int c = nt * 8 + lc * 2;
        *(float2*)&obase[(size_t)r0 * VD + c] = make_float2(o[nt][0] * inv0, o[nt][1] * inv0);
        *(float2*)&obase[(size_t)r1 * VD + c] = make_float2(o[nt][2] * inv1, o[nt][3] * inv1);
    }
}

// ---------------- combine pairs + RMSNorm -------------------------------------
__global__ void combine_kernel(const float* __restrict__ oj, float* __restrict__ att) {
    const int bid = blockIdx.x;
    const int hv = bid & 7;
    const int s  = (bid >> 3) & (S_LEN - 1);
    const int b  = bid >> 14;
    const int d  = threadIdx.x;

    const float lam = g_lambda;
    size_t i0 = (((size_t)(b * NHEAD + 2 * hv)) * S_LEN + s) * VD + d;
    size_t i1 = i0 + (size_t)S_LEN * VD;
    float val = oj[i0] - lam * oj[i1];

    float v2 = val * val;
#pragma unroll
    for (int off = 16; off > 0; off >>= 1)
        v2 += __shfl_xor_sync(0xffffffffu, v2, off);
    __shared__ float red[4];
    if ((d & 31) == 0) red[d >> 5] = v2;
    __syncthreads();
    float tot = red[0] + red[1] + red[2] + red[3];
    float rms = rsqrtf(tot * (1.0f / 128.0f) + 1e-5f);
    att[((size_t)(b * S_LEN) + s) * DIMN + hv * VD + d] = val * rms * (1.0f - LAMBDA_INIT);
}

// ---------------- launch ------------------------------------------------------
extern "C" void kernel_launch(void* const* d_in, const int* in_sizes, int n_in,
                              void* d_out, int out_size) {
    const float* x   = (const float*)d_in[0];
    const float* Wq  = (const float*)d_in[1];
    const float* Wk  = (const float*)d_in[2];
    const float* Wv  = (const float*)d_in[3];
    const float* Wo  = (const float*)d_in[4];
    const float* lq1 = (const float*)d_in[5];
    const float* lk1 = (const float*)d_in[6];
    const float* lq2 = (const float*)d_in[7];
    const float* lk2 = (const float*)d_in[8];
    float* out = (float*)d_out;

    float *q_p, *k_p, *v_p, *oj_p, *att_p;
    cudaGetSymbolAddress((void**)&q_p,   g_q);
    cudaGetSymbolAddress((void**)&k_p,   g_k);
    cudaGetSymbolAddress((void**)&v_p,   g_v);
    cudaGetSymbolAddress((void**)&oj_p,  g_oj);
    cudaGetSymbolAddress((void**)&att_p, g_att);

    cudaFuncSetAttribute(flash_mma_kernel, cudaFuncAttributeMaxDynamicSharedMemorySize,
                         FLASH_SMEM_BYTES);

    lambda_kernel<<<1, 32>>>(lq1, lk1, lq2, lk2);

    // fused q/k/v projections: grid.x = 3 matrices x 8 N-blocks
    dim3 gqkv(24, M_TOT / 128);
    gemm_bf16x3<<<gqkv, 256>>>(x, Wq, Wk, Wv, q_p, k_p, v_p,
                               M_TOT, DIMN, DIMN, 0.125f, 1.0f, 1.0f);

    dim3 fgrid(S_LEN / 128, NHEAD, BATCH);
    flash_mma_kernel<<<fgrid, 256, FLASH_SMEM_BYTES>>>(q_p, k_p, v_p, oj_p);

    combine_kernel<<<BATCH * S_LEN * 8, 128>>>(oj_p, att_p);

    dim3 gout(8, M_TOT / 128);
    gemm_bf16x3<<<gout, 256>>>(att_p, Wo, Wo, Wo, out, out, out,
                               M_TOT, DIMN, DIMN, 1.0f, 1.0f, 1.0f);
}

// round 17
// speedup vs baseline: 2.4168x; 1.0553x over previous
#include <cuda_runtime.h>
#include <cuda_bf16.h>
#include <math.h>
#include <stdint.h>

#define DIMN   1024
#define S_LEN  2048
#define BATCH  2
#define NHEAD  16     // 2H attention heads (q/k), dim 64
#define HD     64
#define VD     128    // v head dim (2*hd)
#define M_TOT  (BATCH*S_LEN)   // 4096

#define LAMBDA_INIT 0.70082066706704805f

// ---------------- scratch (static device memory; no runtime allocs) ----------
__device__ float g_q[(size_t)BATCH*S_LEN*DIMN];
__device__ float g_k[(size_t)BATCH*S_LEN*DIMN];
__device__ float g_v[(size_t)BATCH*S_LEN*DIMN];
__device__ float g_oj[(size_t)BATCH*NHEAD*S_LEN*VD];   // per-attn-head O
__device__ float g_att[(size_t)BATCH*S_LEN*DIMN];      // combined, pre-Wo
__device__ float g_lambda;

// ---------------- lambda ------------------------------------------------------
__global__ void lambda_kernel(const float* __restrict__ lq1, const float* __restrict__ lk1,
                              const float* __restrict__ lq2, const float* __restrict__ lk2) {
    if (threadIdx.x == 0) {
        float s1 = 0.f, s2 = 0.f;
        for (int i = 0; i < HD; i++) { s1 += lq1[i]*lk1[i]; s2 += lq2[i]*lk2[i]; }
        g_lambda = expf(s1) - expf(s2) + LAMBDA_INIT;
    }
}

// ---------------- mma helpers -------------------------------------------------
__device__ __forceinline__ uint32_t f2tf32(float x) {
    uint32_t r;
    asm("cvt.rna.tf32.f32 %0, %1;" : "=r"(r) : "f"(x));
    return r;
}
__device__ __forceinline__ float tf32hi(float x) {
    return __uint_as_float(f2tf32(x));
}

__device__ __forceinline__ void mma_tf32(float* c,
                                         uint32_t a0, uint32_t a1, uint32_t a2, uint32_t a3,
                                         uint32_t b0, uint32_t b1) {
    asm volatile("mma.sync.aligned.m16n8k8.row.col.f32.tf32.tf32.f32 "
                 "{%0,%1,%2,%3}, {%4,%5,%6,%7}, {%8,%9}, {%0,%1,%2,%3};\n"
                 : "+f"(c[0]), "+f"(c[1]), "+f"(c[2]), "+f"(c[3])
                 : "r"(a0), "r"(a1), "r"(a2), "r"(a3), "r"(b0), "r"(b1));
}

__device__ __forceinline__ void mma_bf16(float* c,
                                         uint32_t a0, uint32_t a1, uint32_t a2, uint32_t a3,
                                         uint32_t b0, uint32_t b1) {
    asm volatile("mma.sync.aligned.m16n8k16.row.col.f32.bf16.bf16.f32 "
                 "{%0,%1,%2,%3}, {%4,%5,%6,%7}, {%8,%9}, {%0,%1,%2,%3};\n"
                 : "+f"(c[0]), "+f"(c[1]), "+f"(c[2]), "+f"(c[3])
                 : "r"(a0), "r"(a1), "r"(a2), "r"(a3), "r"(b0), "r"(b1));
}

#define LDSM4(r0, r1, r2, r3, addr) \
    asm volatile("ldmatrix.sync.aligned.m8n8.x4.shared.b16 {%0,%1,%2,%3}, [%4];" \
                 : "=r"(r0), "=r"(r1), "=r"(r2), "=r"(r3) : "r"(addr))

// split float2 -> packed bf16x2 hi + lo  (low 16 bits = first element)
__device__ __forceinline__ void split2bf16(float x, float y, uint32_t& hi, uint32_t& lo) {
    __nv_bfloat162 h = __floats2bfloat162_rn(x, y);
    float2 hf = __bfloat1622float2(h);
    __nv_bfloat162 l = __floats2bfloat162_rn(x - hf.x, y - hf.y);
    hi = *(uint32_t*)&h;
    lo = *(uint32_t*)&l;
}

// ---------------- NT GEMM via bf16-3x tensor cores + ldmatrix -----------------
// C[m,n] = alpha * sum_k A[m,k]*B[n,k].  BM=BN=128, BK=16, 256 threads (8 warps
// in 2(M)x4(N)); each warp owns 64x32 = 4x4 grid of m16n8k16 mmas (3 per k16).
// Up to 3 B/C matrices in one launch (shared A): sel = blockIdx.x>>3.
__global__ __launch_bounds__(256, 2) void gemm_bf16x3(const float* __restrict__ A,
                                                      const float* __restrict__ B0,
                                                      const float* __restrict__ B1,
                                                      const float* __restrict__ B2,
                                                      float* __restrict__ C0,
                                                      float* __restrict__ C1,
                                                      float* __restrict__ C2,
                                                      int M, int N, int K,
                                                      float al0, float al1, float al2) {
    // packed bf16x2 tiles: 8 used pair-cols + 4 pad -> stride 12 (conflict-free frags)
    __shared__ uint32_t Ah[128][12], Al[128][12];
    __shared__ uint32_t Bh[128][12], Bl[128][12];

    const int sel = blockIdx.x >> 3;
    const float* B = (sel == 0) ? B0 : (sel == 1) ? B1 : B2;
    float*       C = (sel == 0) ? C0 : (sel == 1) ? C1 : C2;
    const float alpha = (sel == 0) ? al0 : (sel == 1) ? al1 : al2;

    const int tid  = threadIdx.x;
    const int lane = tid & 31;
    const int w    = tid >> 5;
    const int warp_m = (w & 1) * 64;
    const int warp_n = (w >> 1) * 32;
    const int lr = lane >> 2;              // 0..7
    const int lc = lane & 3;               // 0..3
    const int bm0 = blockIdx.y * 128, bn0 = (blockIdx.x & 7) * 128;

    const int ldr  = tid >> 2;             // 0..63
    const int ldr2 = ldr + 64;
    const int pc   = (tid & 3) << 1;       // pair-col base (0,2,4,6)
    const int ldc  = (tid & 3) << 2;       // float col base

    // ldmatrix per-lane addressing: matrix j = lane>>3, row-in-matrix = lane&7
    const int j  = lane >> 3;
    const int ri = lane & 7;
    const uint32_t uAh = (uint32_t)__cvta_generic_to_shared(Ah);
    const uint32_t uAl = (uint32_t)__cvta_generic_to_shared(Al);
    const uint32_t uBh = (uint32_t)__cvta_generic_to_shared(Bh);
    const uint32_t uBl = (uint32_t)__cvta_generic_to_shared(Bl);
    // A: rows + 8*(j&1), pairs + 4*(j>>1)
    const uint32_t offA = ((uint32_t)(warp_m + (j & 1) * 8 + ri) * 12 + (j >> 1) * 4) * 4;
    // B: nt rows + 8*(j>>1), pairs + 4*(j&1)
    const uint32_t offB = ((uint32_t)(warp_n + (j >> 1) * 8 + ri) * 12 + (j & 1) * 4) * 4;

    float acc[4][4][4];
#pragma unroll
    for (int i = 0; i < 4; i++)
#pragma unroll
        for (int jj = 0; jj < 4; jj++)
#pragma unroll
            for (int r = 0; r < 4; r++) acc[i][jj][r] = 0.f;

    // prefetch first k-tile into registers
    float4 ra0 = *(const float4*)&A[(size_t)(bm0 + ldr ) * K + ldc];
    float4 ra1 = *(const float4*)&A[(size_t)(bm0 + ldr2) * K + ldc];
    float4 rb0 = *(const float4*)&B[(size_t)(bn0 + ldr ) * K + ldc];
    float4 rb1 = *(const float4*)&B[(size_t)(bn0 + ldr2) * K + ldc];

    for (int k0 = 0; k0 < K; k0 += 16) {
        // split + commit staged registers to smem (packed bf16x2)
        {
            uint32_t h0, l0, h1, l1;
            split2bf16(ra0.x, ra0.y, h0, l0); split2bf16(ra0.z, ra0.w, h1, l1);
            Ah[ldr ][pc] = h0; Ah[ldr ][pc+1] = h1; Al[ldr ][pc] = l0; Al[ldr ][pc+1] = l1;
            split2bf16(ra1.x, ra1.y, h0, l0); split2bf16(ra1.z, ra1.w, h1, l1);
            Ah[ldr2][pc] = h0; Ah[ldr2][pc+1] = h1; Al[ldr2][pc] = l0; Al[ldr2][pc+1] = l1;
            split2bf16(rb0.x, rb0.y, h0, l0); split2bf16(rb0.z, rb0.w, h1, l1);
            Bh[ldr ][pc] = h0; Bh[ldr ][pc+1] = h1; Bl[ldr ][pc] = l0; Bl[ldr ][pc+1] = l1;
            split2bf16(rb1.x, rb1.y, h0, l0); split2bf16(rb1.z, rb1.w, h1, l1);
            Bh[ldr2][pc] = h0; Bh[ldr2][pc+1] = h1; Bl[ldr2][pc] = l0; Bl[ldr2][pc+1] = l1;
        }
        __syncthreads();

        // issue next tile's global loads (overlap with mma body)
        if (k0 + 16 < K) {
            int kn = k0 + 16;
            ra0 = *(const float4*)&A[(size_t)(bm0 + ldr ) * K + kn + ldc];
            ra1 = *(const float4*)&A[(size_t)(bm0 + ldr2) * K + kn + ldc];
            rb0 = *(const float4*)&B[(size_t)(bn0 + ldr ) * K + kn + ldc];
            rb1 = *(const float4*)&B[(size_t)(bn0 + ldr2) * K + kn + ldc];
        }

        // one k16 step per tile; fragments via ldmatrix
        {
            uint32_t bh[4][2], bl[4][2];
#pragma unroll
            for (int g = 0; g < 2; g++) {                 // nt pair group
                uint32_t ob = offB + (uint32_t)g * (16 * 12 * 4);
                LDSM4(bh[2*g][0], bh[2*g][1], bh[2*g+1][0], bh[2*g+1][1], uBh + ob);
                LDSM4(bl[2*g][0], bl[2*g][1], bl[2*g+1][0], bl[2*g+1][1], uBl + ob);
            }
#pragma unroll
            for (int mt = 0; mt < 4; mt++) {
                uint32_t oa = offA + (uint32_t)mt * (16 * 12 * 4);
                uint32_t ah0, ah1, ah2, ah3, al0, al1, al2, al3;
                LDSM4(ah0, ah1, ah2, ah3, uAh + oa);
                LDSM4(al0, al1, al2, al3, uAl + oa);
#pragma unroll
                for (int nt = 0; nt < 4; nt++) {
                    mma_bf16(acc[mt][nt], ah0, ah1, ah2, ah3, bh[nt][0], bh[nt][1]);
                    mma_bf16(acc[mt][nt], ah0, ah1, ah2, ah3, bl[nt][0], bl[nt][1]);
                    mma_bf16(acc[mt][nt], al0, al1, al2, al3, bh[nt][0], bh[nt][1]);
                }
            }
        }
        __syncthreads();
    }

    // epilogue: c0,c1 at (row lr, col lc*2 +0/1), c2,c3 at (row lr+8, ...)
#pragma unroll
    for (int mt = 0; mt < 4; mt++) {
#pragma unroll
        for (int nt = 0; nt < 4; nt++) {
            int row = bm0 + warp_m + mt * 16 + lr;
            int col = bn0 + warp_n + nt * 8 + lc * 2;
            float2 lo = make_float2(alpha * acc[mt][nt][0], alpha * acc[mt][nt][1]);
            float2 hi = make_float2(alpha * acc[mt][nt][2], alpha * acc[mt][nt][3]);
            *(float2*)&C[(size_t)row * N + col]       = lo;
            *(float2*)&C[(size_t)(row + 8) * N + col] = hi;
        }
    }
}

// ---------------- flash attention, tensor-core version ------------------------
// BM=128 q rows, BN=64 keys/iter, hd=64, VD=128. 256 threads = 8 warps, each
// warp owns 16 q rows (softmax state warp-local). QK = bf16-3x (m16n8k16) with
// ldmatrix fragment loads, PV = 1xTF32 (m16n8k8).
// smem: Qh/Ql u32[128][36], Kh/Kl u32[64][36], V f32[64][136], P f32[128][68]
#define FL_QP 36       // pair stride for Q/K (32 pairs used + pad; 16B-aligned rows)
#define FL_VS 136
#define FL_PS 68
#define OFF_QH 0
#define OFF_QL (OFF_QH + 128*FL_QP)
#define OFF_KH (OFF_QL + 128*FL_QP)
#define OFF_KL (OFF_KH + 64*FL_QP)
#define OFF_V  (OFF_KL + 64*FL_QP)
#define OFF_P  (OFF_V  + 64*FL_VS)
#define FLASH_SMEM_WORDS (OFF_P + 128*FL_PS)
#define FLASH_SMEM_BYTES (FLASH_SMEM_WORDS * 4)

__global__ __launch_bounds__(256, 1) void flash_mma_kernel(const float* __restrict__ q,
                                                           const float* __restrict__ k,
                                                           const float* __restrict__ v,
                                                           float* __restrict__ oj) {
    extern __shared__ uint32_t smw[];
    uint32_t (*Qh)[FL_QP] = (uint32_t (*)[FL_QP])(smw + OFF_QH);
    uint32_t (*Ql)[FL_QP] = (uint32_t (*)[FL_QP])(smw + OFF_QL);
    uint32_t (*Kh)[FL_QP] = (uint32_t (*)[FL_QP])(smw + OFF_KH);
    uint32_t (*Kl)[FL_QP] = (uint32_t (*)[FL_QP])(smw + OFF_KL);
    float    (*Vs)[FL_VS] = (float    (*)[FL_VS])(smw + OFF_V);
    float    (*Ps)[FL_PS] = (float    (*)[FL_PS])(smw + OFF_P);

    const int tid  = threadIdx.x;
    const int lane = tid & 31;
    const int w    = tid >> 5;
    const int wm   = w * 16;               // warp's 16 q rows
    const int lr   = lane >> 2;            // 0..7
    const int lc   = lane & 3;             // 0..3
    const int qb   = (gridDim.x - 1) - blockIdx.x;   // big tiles first
    const int h    = blockIdx.y;
    const int b    = blockIdx.z;
    const int hv   = h >> 1;

    // ldmatrix addressing
    const int j  = lane >> 3;
    const int ri = lane & 7;
    const uint32_t uQh = (uint32_t)__cvta_generic_to_shared(smw + OFF_QH);
    const uint32_t uQl = (uint32_t)__cvta_generic_to_shared(smw + OFF_QL);
    const uint32_t uKh = (uint32_t)__cvta_generic_to_shared(smw + OFF_KH);
    const uint32_t uKl = (uint32_t)__cvta_generic_to_shared(smw + OFF_KL);
    const uint32_t offQ = ((uint32_t)(wm + (j & 1) * 8 + ri) * FL_QP + (j >> 1) * 4) * 4;
    const uint32_t offK = ((uint32_t)((j >> 1) * 8 + ri) * FL_QP + (j & 1) * 4) * 4;

    const float* qbase = q + ((size_t)(b * S_LEN + qb * 128)) * DIMN + h * HD;
    const float* kbase = k + (size_t)b * S_LEN * DIMN + h * HD;
    const float* vbase = v + (size_t)b * S_LEN * DIMN + hv * VD;

    // load Q tile 128x64, bf16 split. 2048 float4, 8 per thread.
#pragma unroll
    for (int u = 0; u < 8; u++) {
        int idx = tid + u * 256;
        int row = idx >> 4;
        int c4  = (idx & 15) << 2;
        int pb  = (idx & 15) << 1;
        float4 x = *(const float4*)&qbase[(size_t)row * DIMN + c4];
        uint32_t h0, l0, h1, l1;
        split2bf16(x.x, x.y, h0, l0);
        split2bf16(x.z, x.w, h1, l1);
        Qh[row][pb] = h0; Qh[row][pb + 1] = h1;
        Ql[row][pb] = l0; Ql[row][pb + 1] = l1;
    }

    float mrow[2], lrow[2];
    float o[16][4];
    mrow[0] = mrow[1] = -1e30f;
    lrow[0] = lrow[1] = 0.f;
#pragma unroll
    for (int i = 0; i < 16; i++)
#pragma unroll
        for (int r = 0; r < 4; r++) o[i][r] = 0.f;

    const int ktiles = 2 * qb + 2;
    for (int kt = 0; kt < ktiles; kt++) {
        __syncthreads();
        // load K tile 64x64 (bf16 split): 1024 float4, 4/thread
#pragma unroll
        for (int u = 0; u < 4; u++) {
            int idx = tid + u * 256;
            int row = idx >> 4;
            int c4  = (idx & 15) << 2;
            int pb  = (idx & 15) << 1;
            float4 x = *(const float4*)&kbase[(size_t)(kt * 64 + row) * DIMN + c4];
            uint32_t h0, l0, h1, l1;
            split2bf16(x.x, x.y, h0, l0);
            split2bf16(x.z, x.w, h1, l1);
            Kh[row][pb] = h0; Kh[row][pb + 1] = h1;
            Kl[row][pb] = l0; Kl[row][pb + 1] = l1;
        }
        // load V tile 64x128 (tf32-rounded): 2048 float4, 8/thread
#pragma unroll
        for (int u = 0; u < 8; u++) {
            int idx = tid + u * 256;
            int row = idx >> 5;
            int c4  = (idx & 31) << 2;
            float4 x = *(const float4*)&vbase[(size_t)(kt * 64 + row) * DIMN + c4];
            x.x=tf32hi(x.x); x.y=tf32hi(x.y); x.z=tf32hi(x.z); x.w=tf32hi(x.w);
            *(float4*)&Vs[row][c4] = x;
        }
        __syncthreads();

        // ---- S = Q K^T via bf16-3x: 8 n8-tiles x 4 k16-steps, ldmatrix ----
        float s[8][4];
#pragma unroll
        for (int nt = 0; nt < 8; nt++)
#pragma unroll
            for (int r = 0; r < 4; r++) s[nt][r] = 0.f;

#pragma unroll
        for (int ks = 0; ks < 4; ks++) {
            uint32_t kofs = (uint32_t)(8 * ks) * 4;      // pair base 8*ks
            uint32_t ah0, ah1, ah2, ah3, al0, al1, al2, al3;
            LDSM4(ah0, ah1, ah2, ah3, uQh + offQ + kofs);
            LDSM4(al0, al1, al2, al3, uQl + offQ + kofs);
#pragma unroll
            for (int g = 0; g < 4; g++) {                // nt pair groups
                uint32_t ob = offK + kofs + (uint32_t)g * (16 * FL_QP * 4);
                uint32_t bh0, bh1, bh2, bh3, bl0, bl1, bl2, bl3;
                LDSM4(bh0, bh1, bh2, bh3, uKh + ob);
                LDSM4(bl0, bl1, bl2, bl3, uKl + ob);
                mma_bf16(s[2*g],   ah0, ah1, ah2, ah3, bh0, bh1);
                mma_bf16(s[2*g],   ah0, ah1, ah2, ah3, bl0, bl1);
                mma_bf16(s[2*g],   al0, al1, al2, al3, bh0, bh1);
                mma_bf16(s[2*g+1], ah0, ah1, ah2, ah3, bh2, bh3);
                mma_bf16(s[2*g+1], ah0, ah1, ah2, ah3, bl2, bl3);
                mma_bf16(s[2*g+1], al0, al1, al2, al3, bh2, bh3);
            }
        }

        // ---- causal mask on diagonal tiles ----
        if (kt >= 2 * qb) {
            int koff = kt * 64 - qb * 128;   // 0 or 64
            int r0 = wm + lr, r1 = wm + lr + 8;
#pragma unroll
            for (int nt = 0; nt < 8; nt++) {
                int c0 = koff + nt * 8 + lc * 2;
                int c1 = c0 + 1;
                if (c0 > r0) s[nt][0] = -1e30f;
                if (c1 > r0) s[nt][1] = -1e30f;
                if (c0 > r1) s[nt][2] = -1e30f;
                if (c1 > r1) s[nt][3] = -1e30f;
            }
        }

        // ---- online softmax (rows lr and lr+8, quad-wide reductions) ----
#pragma unroll
        for (int half = 0; half < 2; half++) {
            float mt = -1e30f;
#pragma unroll
            for (int nt = 0; nt < 8; nt++)
                mt = fmaxf(mt, fmaxf(s[nt][2*half], s[nt][2*half+1]));
            mt = fmaxf(mt, __shfl_xor_sync(0xffffffffu, mt, 1));
            mt = fmaxf(mt, __shfl_xor_sync(0xffffffffu, mt, 2));
            float mn = fmaxf(mrow[half], mt);
            float sc = __expf(mrow[half] - mn);
            float ps = 0.f;
#pragma unroll
            for (int nt = 0; nt < 8; nt++) {
                float e0 = __expf(s[nt][2*half]   - mn);
                float e1 = __expf(s[nt][2*half+1] - mn);
                ps += e0 + e1;
                s[nt][2*half]   = e0;
                s[nt][2*half+1] = e1;
            }
            ps += __shfl_xor_sync(0xffffffffu, ps, 1);
            ps += __shfl_xor_sync(0xffffffffu, ps, 2);
            lrow[half] = lrow[half] * sc + ps;
            mrow[half] = mn;
#pragma unroll
            for (int nt = 0; nt < 16; nt++) {
                o[nt][2*half]   *= sc;
                o[nt][2*half+1] *= sc;
            }
        }

        // ---- stage P (tf32-rounded) to this warp's smem rows ----
        {
            int r0 = wm + lr, r1 = wm + lr + 8;
#pragma unroll
            for (int nt = 0; nt < 8; nt++) {
                int c = nt * 8 + lc * 2;
                Ps[r0][c]     = tf32hi(s[nt][0]);
                Ps[r0][c + 1] = tf32hi(s[nt][1]);
                Ps[r1][c]     = tf32hi(s[nt][2]);
                Ps[r1][c + 1] = tf32hi(s[nt][3]);
            }
        }
        __syncwarp();

        // ---- O += P @ V : 16 vd n8-tiles x 8 k8-steps (tf32) ----
#pragma unroll
        for (int ks = 0; ks < 64; ks += 8) {
            int r0 = wm + lr;
            uint32_t a0 = __float_as_uint(Ps[r0    ][ks + lc]);
            uint32_t a1 = __float_as_uint(Ps[r0 + 8][ks + lc]);
            uint32_t a2 = __float_as_uint(Ps[r0    ][ks + lc + 4]);
            uint32_t a3 = __float_as_uint(Ps[r0 + 8][ks + lc + 4]);
#pragma unroll
            for (int nt = 0; nt < 16; nt++) {
                uint32_t b0 = __float_as_uint(Vs[ks + lc    ][nt * 8 + lr]);
                uint32_t b1 = __float_as_uint(Vs[ks + lc + 4][nt * 8 + lr]);
                mma_tf32(o[nt], a0, a1, a2, a3, b0, b1);
            }
        }
    }

    // ---- epilogue: O /= l, store ----
    float* obase = oj + (((size_t)(b * NHEAD + h)) * S_LEN + qb * 128) * VD;
    float inv0 = 1.f / lrow[0];
    float inv1 = 1.f / lrow[1];
    int r0 = wm + lr, r1 = wm + lr + 8;
#pragma unroll
    for (int nt = 0; nt < 16; nt++) {
        int c = nt * 8 + lc * 2;
        *(float2*)&obase[(size_t)r0 * VD + c] = make_float2(o[nt][0] * inv0, o[nt][1] * inv0);
        *(float2*)&obase[(size_t)r1 * VD + c] = make_float2(o[nt][2] * inv1, o[nt][3] * inv1);
    }
}

// ---------------- combine pairs + RMSNorm -------------------------------------
__global__ void combine_kernel(const float* __restrict__ oj, float* __restrict__ att) {
    const int bid = blockIdx.x;
    const int hv = bid & 7;
    const int s  = (bid >> 3) & (S_LEN - 1);
    const int b  = bid >> 14;
    const int d  = threadIdx.x;

    const float lam = g_lambda;
    size_t i0 = (((size_t)(b * NHEAD + 2 * hv)) * S_LEN + s) * VD + d;
    size_t i1 = i0 + (size_t)S_LEN * VD;
    float val = oj[i0] - lam * oj[i1];

    float v2 = val * val;
#pragma unroll
    for (int off = 16; off > 0; off >>= 1)
        v2 += __shfl_xor_sync(0xffffffffu, v2, off);
    __shared__ float red[4];
    if ((d & 31) == 0) red[d >> 5] = v2;
    __syncthreads();
    float tot = red[0] + red[1] + red[2] + red[3];
    float rms = rsqrtf(tot * (1.0f / 128.0f) + 1e-5f);
    att[((size_t)(b * S_LEN) + s) * DIMN + hv * VD + d] = val * rms * (1.0f - LAMBDA_INIT);
}

// ---------------- launch ------------------------------------------------------
extern "C" void kernel_launch(void* const* d_in, const int* in_sizes, int n_in,
                              void* d_out, int out_size) {
    const float* x   = (const float*)d_in[0];
    const float* Wq  = (const float*)d_in[1];
    const float* Wk  = (const float*)d_in[2];
    const float* Wv  = (const float*)d_in[3];
    const float* Wo  = (const float*)d_in[4];
    const float* lq1 = (const float*)d_in[5];
    const float* lk1 = (const float*)d_in[6];
    const float* lq2 = (const float*)d_in[7];
    const float* lk2 = (const float*)d_in[8];
    float* out = (float*)d_out;

    float *q_p, *k_p, *v_p, *oj_p, *att_p;
    cudaGetSymbolAddress((void**)&q_p,   g_q);
    cudaGetSymbolAddress((void**)&k_p,   g_k);
    cudaGetSymbolAddress((void**)&v_p,   g_v);
    cudaGetSymbolAddress((void**)&oj_p,  g_oj);
    cudaGetSymbolAddress((void**)&att_p, g_att);

    cudaFuncSetAttribute(flash_mma_kernel, cudaFuncAttributeMaxDynamicSharedMemorySize,
                         FLASH_SMEM_BYTES);

    lambda_kernel<<<1, 32>>>(lq1, lk1, lq2, lk2);

    // fused q/k/v projections: grid.x = 3 matrices x 8 N-blocks
    dim3 gqkv(24, M_TOT / 128);
    gemm_bf16x3<<<gqkv, 256>>>(x, Wq, Wk, Wv, q_p, k_p, v_p,
                               M_TOT, DIMN, DIMN, 0.125f, 1.0f, 1.0f);

    dim3 fgrid(S_LEN / 128, NHEAD, BATCH);
    flash_mma_kernel<<<fgrid, 256, FLASH_SMEM_BYTES>>>(q_p, k_p, v_p, oj_p);

    combine_kernel<<<BATCH * S_LEN * 8, 128>>>(oj_p, att_p);

    dim3 gout(8, M_TOT / 128);
    gemm_bf16x3<<<gout, 256>>>(att_p, Wo, Wo, Wo, out, out, out,
                               M_TOT, DIMN, DIMN, 1.0f, 1.0f, 1.0f);
}